// round 5
// baseline (speedup 1.0000x reference)
#include <cuda_runtime.h>
#include <cstdint>

#define T_STEPS 16
#define AA 64
#define BB 64
#define NN 12
#define BATCH 4096
#define ZS 100
#define ENC 400
#define DEC 400

// ---------------- device scratch (no allocs allowed) ----------------
__device__ float g_henc[BATCH * ENC];
__device__ float g_senc[BATCH * ENC];
__device__ float g_hdec[BATCH * DEC];
__device__ float g_sdec[BATCH * DEC];
__device__ float g_encin[BATCH * 1088];   // [r(288) | h_dec(400) | h_enc(400)]
__device__ float g_decin[BATCH * 512];    // [z(100) | h_dec(400) | pad(12)]
__device__ float g_gates[BATCH * 1600];
__device__ float g_musig[BATCH * 200];    // [mu(100) | logsig(100)]
__device__ float g_Fx[BATCH * NN * AA];
__device__ float g_Fy[BATCH * NN * BB];
__device__ float g_gamma[BATCH];
__device__ float g_wr[BATCH * NN * NN];

__device__ __forceinline__ float sigm(float x) { return 1.0f / (1.0f + expf(-x)); }

__device__ __forceinline__ uint32_t f2tf32(float x) {
    uint32_t r;
    asm("cvt.rna.tf32.f32 %0, %1;" : "=r"(r) : "f"(x));
    return r;
}

__device__ __forceinline__ void mma_tf32(float* d, const uint32_t* a, const uint32_t* b) {
    asm volatile(
        "mma.sync.aligned.m16n8k8.row.col.f32.tf32.tf32.f32 "
        "{%0,%1,%2,%3}, {%4,%5,%6,%7}, {%8,%9}, {%0,%1,%2,%3};\n"
        : "+f"(d[0]), "+f"(d[1]), "+f"(d[2]), "+f"(d[3])
        : "r"(a[0]), "r"(a[1]), "r"(a[2]), "r"(a[3]), "r"(b[0]), "r"(b[1]));
}

// ================= tensor-core GEMM (3xTF32 mma.sync, ~fp32 accuracy) =======
// C[M, Nout] = A[M, Ktot] @ [W1 | W2]^T + b1 (+ b2)
// A row-major (lda), W row-major (Nout x K). M mult of 128.
// Block tile 128x64x32, 256 threads (8 warps: 4 along M, 2 along N).
// Each operand split hi/lo (tf32 + residual); 3 MMAs per product for fp32-like
// precision. SMEM: As[k][m] stride 136, Bs[k][n] stride 72, XOR (x ^ (k & 28)).
#define A_PLANE 4352                       // 32*136 words
#define B_PLANE 2304                       // 32*72 words
#define GEMM_SMEM_BYTES ((4 * A_PLANE + 4 * B_PLANE + 64) * 4)

__global__ __launch_bounds__(256) void gemm_mma(
    const float* __restrict__ A, int lda, int Ktot,
    const float* __restrict__ W1, int K1,
    const float* __restrict__ W2, int K2,
    const float* __restrict__ b1, const float* __restrict__ b2,
    float* __restrict__ C, int ldc, int Nout)
{
    extern __shared__ uint32_t sm[];
    uint32_t* Asb = sm;                          // 2 bufs x (hi,lo) planes
    uint32_t* Bsb = sm + 4 * A_PLANE;
    float* sbias = (float*)(sm + 4 * A_PLANE + 4 * B_PLANE);

    const int tid  = threadIdx.x;
    const int lane = tid & 31;
    const int w    = tid >> 5;
    const int r    = lane >> 2;          // 0..7
    const int j    = lane & 3;           // 0..3
    const int wm   = (w >> 1) * 32;      // warp M offset in tile
    const int wn   = (w & 1) * 32;       // warp N offset in tile
    const int m0   = blockIdx.y * 128;
    const int n0   = blockIdx.x * 64;
    const int K12  = K1 + K2;
    const int S    = (Ktot + 31) >> 5;

    if (tid < 64) {
        int n = n0 + tid;
        float bv = 0.f;
        if (n < Nout) { bv = b1[n]; if (b2) bv += b2[n]; }
        sbias[tid] = bv;
    }

    float d[2][4][4];
#pragma unroll
    for (int mi = 0; mi < 2; mi++)
#pragma unroll
        for (int ni = 0; ni < 4; ni++)
#pragma unroll
            for (int q = 0; q < 4; q++) d[mi][ni][q] = 0.f;

    float4 pa[4];
    float4 pb[2];
    const float4 f4z = make_float4(0.f, 0.f, 0.f, 0.f);

#define LOAD_GLOBAL(s) {                                                         \
    int k0g = (s) << 5;                                                          \
    _Pragma("unroll")                                                            \
    for (int cI = 0; cI < 4; cI++) {                                             \
        int fidx = tid + (cI << 8);                                              \
        int m = fidx >> 3;                                                       \
        int kg = k0g + ((fidx & 7) << 2);                                        \
        pa[cI] = (kg < Ktot)                                                     \
            ? *(const float4*)(A + (size_t)(m0 + m) * lda + kg) : f4z;           \
    }                                                                            \
    _Pragma("unroll")                                                            \
    for (int cI = 0; cI < 2; cI++) {                                             \
        int fidx = tid + (cI << 8);                                              \
        int n = fidx >> 3;                                                       \
        int kg = k0g + ((fidx & 7) << 2);                                        \
        float4 v = f4z;                                                          \
        int ng = n0 + n;                                                         \
        if (ng < Nout) {                                                         \
            if (kg < K1)       v = *(const float4*)(W1 + (size_t)ng * K1 + kg);  \
            else if (kg < K12) v = *(const float4*)(W2 + (size_t)ng * K2 + (kg - K1)); \
        }                                                                        \
        pb[cI] = v;                                                              \
    } }

#define STORE_SMEM(buf) {                                                        \
    uint32_t* abh = Asb + (buf) * (2 * A_PLANE);                                 \
    uint32_t* abl = abh + A_PLANE;                                               \
    uint32_t* bbh = Bsb + (buf) * (2 * B_PLANE);                                 \
    uint32_t* bbl = bbh + B_PLANE;                                               \
    _Pragma("unroll")                                                            \
    for (int cI = 0; cI < 4; cI++) {                                             \
        int fidx = tid + (cI << 8);                                              \
        int m = fidx >> 3;                                                       \
        int kq = (fidx & 7) << 2;                                                \
        const float* pv = (const float*)&pa[cI];                                 \
        _Pragma("unroll")                                                        \
        for (int u = 0; u < 4; u++) {                                            \
            int k = kq + u;                                                      \
            int idx = k * 136 + (m ^ (k & 28));                                  \
            uint32_t hi = f2tf32(pv[u]);                                         \
            abh[idx] = hi;                                                       \
            abl[idx] = f2tf32(pv[u] - __uint_as_float(hi));                      \
        }                                                                        \
    }                                                                            \
    _Pragma("unroll")                                                            \
    for (int cI = 0; cI < 2; cI++) {                                             \
        int fidx = tid + (cI << 8);                                              \
        int n = fidx >> 3;                                                       \
        int kq = (fidx & 7) << 2;                                                \
        const float* pv = (const float*)&pb[cI];                                 \
        _Pragma("unroll")                                                        \
        for (int u = 0; u < 4; u++) {                                            \
            int k = kq + u;                                                      \
            int idx = k * 72 + (n ^ (k & 28));                                   \
            uint32_t hi = f2tf32(pv[u]);                                         \
            bbh[idx] = hi;                                                       \
            bbl[idx] = f2tf32(pv[u] - __uint_as_float(hi));                      \
        }                                                                        \
    } }

#define COMPUTE(buf) {                                                           \
    const uint32_t* abh = Asb + (buf) * (2 * A_PLANE);                           \
    const uint32_t* abl = abh + A_PLANE;                                         \
    const uint32_t* bbh = Bsb + (buf) * (2 * B_PLANE);                           \
    const uint32_t* bbl = bbh + B_PLANE;                                         \
    _Pragma("unroll")                                                            \
    for (int kk = 0; kk < 32; kk += 8) {                                         \
        int k0j = kk + j, k1j = k0j + 4;                                         \
        int f0 = k0j & 28, f1 = k1j & 28;                                        \
        uint32_t afh[2][4], afl[2][4];                                           \
        uint32_t bfh[4][2], bfl[4][2];                                           \
        _Pragma("unroll")                                                        \
        for (int mi = 0; mi < 2; mi++) {                                         \
            int mb = wm + mi * 16 + r;                                           \
            int i00 = k0j * 136 + (mb ^ f0);                                     \
            int i01 = k0j * 136 + ((mb + 8) ^ f0);                               \
            int i10 = k1j * 136 + (mb ^ f1);                                     \
            int i11 = k1j * 136 + ((mb + 8) ^ f1);                               \
            afh[mi][0] = abh[i00]; afh[mi][1] = abh[i01];                        \
            afh[mi][2] = abh[i10]; afh[mi][3] = abh[i11];                        \
            afl[mi][0] = abl[i00]; afl[mi][1] = abl[i01];                        \
            afl[mi][2] = abl[i10]; afl[mi][3] = abl[i11];                        \
        }                                                                        \
        _Pragma("unroll")                                                        \
        for (int ni = 0; ni < 4; ni++) {                                         \
            int nb = wn + ni * 8 + r;                                            \
            int i0 = k0j * 72 + (nb ^ f0);                                       \
            int i1 = k1j * 72 + (nb ^ f1);                                       \
            bfh[ni][0] = bbh[i0]; bfh[ni][1] = bbh[i1];                          \
            bfl[ni][0] = bbl[i0]; bfl[ni][1] = bbl[i1];                          \
        }                                                                        \
        _Pragma("unroll")                                                        \
        for (int mi = 0; mi < 2; mi++)                                           \
            _Pragma("unroll")                                                    \
            for (int ni = 0; ni < 4; ni++) {                                     \
                mma_tf32(d[mi][ni], afh[mi], bfl[ni]);                           \
                mma_tf32(d[mi][ni], afl[mi], bfh[ni]);                           \
                mma_tf32(d[mi][ni], afh[mi], bfh[ni]);                           \
            }                                                                    \
    } }

    LOAD_GLOBAL(0);
    STORE_SMEM(0);
    __syncthreads();

    for (int s = 1; s < S; s++) {
        LOAD_GLOBAL(s);
        COMPUTE((s - 1) & 1);
        STORE_SMEM(s & 1);
        __syncthreads();
    }
    COMPUTE((S - 1) & 1);

    // epilogue
#pragma unroll
    for (int mi = 0; mi < 2; mi++) {
        int row = m0 + wm + mi * 16 + r;
#pragma unroll
        for (int ni = 0; ni < 4; ni++) {
            int col = wn + ni * 8 + 2 * j;
            int gcol = n0 + col;
            if (gcol < Nout) {
                float bx = sbias[col], by = sbias[col + 1];
                *(float2*)(C + (size_t)row * ldc + gcol) =
                    make_float2(d[mi][ni][0] + bx, d[mi][ni][1] + by);
                *(float2*)(C + (size_t)(row + 8) * ldc + gcol) =
                    make_float2(d[mi][ni][2] + bx, d[mi][ni][3] + by);
            }
        }
    }

#undef LOAD_GLOBAL
#undef STORE_SMEM
#undef COMPUTE
}

// ---------------- zero ----------------
__global__ void zero_kernel(float* p, int n) {
    int i = blockIdx.x * blockDim.x + threadIdx.x;
    int stride = gridDim.x * blockDim.x;
    for (; i < n; i += stride) p[i] = 0.0f;
}

// ---------------- attention filters ----------------
__global__ void attn_kernel(const float* __restrict__ hdec,
                            const float* __restrict__ w_attn,
                            const float* __restrict__ b_attn,
                            float* __restrict__ Fx, float* __restrict__ Fy,
                            float* __restrict__ gma,
                            const float* __restrict__ henc,
                            float* __restrict__ encin, int copy_states)
{
    int b = blockIdx.x;
    int tid = threadIdx.x;
    __shared__ float red[5][129];
    __shared__ float p[5];
    __shared__ float Fbuf[NN * 64];
    __shared__ float rsum[NN];

    const float* h = hdec + (size_t)b * DEC;
    float acc[5] = {0.f, 0.f, 0.f, 0.f, 0.f};
    for (int k = tid; k < DEC; k += 128) {
        float hv = h[k];
#pragma unroll
        for (int jj = 0; jj < 5; jj++) acc[jj] += hv * w_attn[jj * DEC + k];
    }
#pragma unroll
    for (int jj = 0; jj < 5; jj++) red[jj][tid] = acc[jj];
    __syncthreads();
    if (tid < 5) {
        float s = 0.f;
        for (int i = 0; i < 128; i++) s += red[tid][i];
        p[tid] = s + b_attn[tid];
    }
    __syncthreads();

    float gx     = 32.5f * (p[0] + 1.0f);
    float gy     = 32.5f * (p[1] + 1.0f);
    float sigma2 = expf(p[2]);
    float delta  = (63.0f / 11.0f) * expf(p[3]);
    float gamma  = expf(p[4]);
    float inv2s2 = 1.0f / (2.0f * sigma2);

    for (int e = tid; e < NN * 64; e += 128) {
        int n = e >> 6, a = e & 63;
        float mu = ((float)n - 6.5f) * delta + gx;
        float t = ((float)a - mu) * inv2s2;
        Fbuf[e] = expf(-t * t);
    }
    __syncthreads();
    if (tid < NN) {
        float s = 0.f;
        for (int a = 0; a < 64; a++) s += Fbuf[tid * 64 + a];
        rsum[tid] = 1.0f / (s + 1e-9f);
    }
    __syncthreads();
    for (int e = tid; e < NN * 64; e += 128)
        Fx[(size_t)b * (NN * 64) + e] = Fbuf[e] * rsum[e >> 6];
    __syncthreads();

    for (int e = tid; e < NN * 64; e += 128) {
        int n = e >> 6, a = e & 63;
        float mu = ((float)n - 6.5f) * delta + gy;
        float t = ((float)a - mu) * inv2s2;
        Fbuf[e] = expf(-t * t);
    }
    __syncthreads();
    if (tid < NN) {
        float s = 0.f;
        for (int a = 0; a < 64; a++) s += Fbuf[tid * 64 + a];
        rsum[tid] = 1.0f / (s + 1e-9f);
    }
    __syncthreads();
    for (int e = tid; e < NN * 64; e += 128)
        Fy[(size_t)b * (NN * 64) + e] = Fbuf[e] * rsum[e >> 6];

    if (tid == 0) gma[b] = gamma;

    if (copy_states) {
        float* ei = encin + (size_t)b * 1088;
        const float* he = henc + (size_t)b * ENC;
        for (int k = tid; k < 400; k += 128) {
            ei[288 + k] = h[k];
            ei[688 + k] = he[k];
        }
    }
}

// ---------------- glimpse (read) ----------------
__global__ void glimpse_kernel(const float* __restrict__ x,
                               const float* __restrict__ c,
                               const float* __restrict__ Fxg,
                               const float* __restrict__ Fyg,
                               const float* __restrict__ gma,
                               float* __restrict__ encin)
{
    int b = blockIdx.x;
    int tid = threadIdx.x;
    __shared__ float xs[4096];
    __shared__ float xh[4096];
    __shared__ float sFy[NN * 64];
    __shared__ float sFx[NN * 65];
    __shared__ float tmp[2][NN * 64];

    const float* xb = x + (size_t)b * 4096;
    const float* cb = c + (size_t)b * 4096;
    for (int i = tid; i < 4096; i += 256) {
        float xv = xb[i];
        float cv = cb[i];
        xs[i] = xv;
        xh[i] = xv - sigm(cv);
    }
    for (int i = tid; i < NN * 64; i += 256) {
        sFy[i] = Fyg[(size_t)b * (NN * 64) + i];
        int n = i >> 6, a = i & 63;
        sFx[n * 65 + a] = Fxg[(size_t)b * (NN * 64) + i];
    }
    __syncthreads();

    for (int e = tid; e < 2 * NN * 64; e += 256) {
        int img = (e >= NN * 64) ? 1 : 0;
        int rem = e - img * NN * 64;
        int n = rem >> 6, a = rem & 63;
        const float* src = img ? xh : xs;
        const float* fyr = &sFy[n * 64];
        float acc = 0.f;
#pragma unroll 8
        for (int bi = 0; bi < 64; bi++) acc += fyr[bi] * src[bi * 64 + a];
        tmp[img][rem] = acc;
    }
    __syncthreads();

    float gamma = gma[b];
    for (int o = tid; o < 2 * NN * NN; o += 256) {
        int img = (o >= NN * NN) ? 1 : 0;
        int rem = o - img * NN * NN;
        int n = rem / NN, m = rem % NN;
        const float* tr = &tmp[img][n * 64];
        const float* fxr = &sFx[m * 65];
        float acc = 0.f;
#pragma unroll 8
        for (int a = 0; a < 64; a++) acc += tr[a] * fxr[a];
        encin[(size_t)b * 1088 + o] = acc * gamma;
    }
}

// ---------------- canvas write ----------------
__global__ void write_kernel(const float* __restrict__ wrg,
                             const float* __restrict__ Fxg,
                             const float* __restrict__ Fyg,
                             const float* __restrict__ gma,
                             float* __restrict__ c)
{
    int b = blockIdx.x;
    int tid = threadIdx.x;
    __shared__ float sFy[NN * 64];
    __shared__ float sFx[NN * 64];
    __shared__ float sw[NN * NN];
    __shared__ float tmp[NN * 64];

    for (int i = tid; i < NN * 64; i += 256) {
        sFy[i] = Fyg[(size_t)b * (NN * 64) + i];
        sFx[i] = Fxg[(size_t)b * (NN * 64) + i];
    }
    if (tid < NN * NN) sw[tid] = wrg[(size_t)b * (NN * NN) + tid];
    __syncthreads();

    for (int e = tid; e < NN * 64; e += 256) {
        int m = e >> 6, Bi = e & 63;
        float acc = 0.f;
#pragma unroll
        for (int n = 0; n < NN; n++) acc += sFy[n * 64 + Bi] * sw[n * NN + m];
        tmp[e] = acc;
    }
    __syncthreads();

    float invg = 1.0f / gma[b];
    float* cb = c + (size_t)b * 4096;
    for (int p = tid; p < 4096; p += 256) {
        int Bi = p >> 6, Ai = p & 63;
        float acc = 0.f;
#pragma unroll
        for (int m = 0; m < NN; m++) acc += tmp[m * 64 + Bi] * sFx[m * 64 + Ai];
        cb[p] += acc * invg;
    }
}

// ---------------- LSTM pointwise ----------------
__global__ void lstm_pw(const float* __restrict__ gates,
                        float* __restrict__ h, float* __restrict__ s)
{
    int idx = blockIdx.x * blockDim.x + threadIdx.x;
    int total = BATCH * 400;
    if (idx >= total) return;
    int b = idx / 400, u = idx - b * 400;
    const float* g = gates + (size_t)b * 1600;
    float gi = g[u], gf = g[400 + u], gg = g[800 + u], go = g[1200 + u];
    float sv = s[idx];
    float c2 = sigm(gf) * sv + sigm(gi) * tanhf(gg);
    float h2 = sigm(go) * tanhf(c2);
    s[idx] = c2;
    h[idx] = h2;
}

// ---------------- z + decoder input assembly (padded to 512) ----------------
__global__ void z_kernel(const float* __restrict__ musig,
                         const float* __restrict__ eps_t,
                         const float* __restrict__ hdec,
                         float* __restrict__ decin)
{
    int idx = blockIdx.x * blockDim.x + threadIdx.x;
    int total = BATCH * 512;
    if (idx >= total) return;
    int b = idx >> 9, j = idx & 511;
    float v;
    if (j < 100) {
        float mu = musig[(size_t)b * 200 + j];
        float ls = musig[(size_t)b * 200 + 100 + j];
        v = mu + expf(ls) * eps_t[(size_t)b * 100 + j];
    } else if (j < 500) {
        v = hdec[(size_t)b * 400 + (j - 100)];
    } else {
        v = 0.f;
    }
    decin[idx] = v;
}

// ---------------- host launcher ----------------
extern "C" void kernel_launch(void* const* d_in, const int* in_sizes, int n_in,
                              void* d_out, int out_size)
{
    const float* x        = (const float*)d_in[0];
    const float* eps      = (const float*)d_in[1];
    const float* w_enc_ih = (const float*)d_in[2];
    const float* w_enc_hh = (const float*)d_in[3];
    const float* b_enc_ih = (const float*)d_in[4];
    const float* b_enc_hh = (const float*)d_in[5];
    const float* w_dec_ih = (const float*)d_in[6];
    const float* w_dec_hh = (const float*)d_in[7];
    const float* b_dec_ih = (const float*)d_in[8];
    const float* b_dec_hh = (const float*)d_in[9];
    const float* w_mu     = (const float*)d_in[10];
    const float* b_mu     = (const float*)d_in[11];
    const float* w_sig    = (const float*)d_in[12];
    const float* b_sig    = (const float*)d_in[13];
    const float* w_attn   = (const float*)d_in[14];
    const float* b_attn   = (const float*)d_in[15];
    const float* w_write  = (const float*)d_in[16];
    const float* b_write  = (const float*)d_in[17];
    float* c = (float*)d_out;

    float *p_henc, *p_senc, *p_hdec, *p_sdec, *p_encin, *p_decin;
    float *p_gates, *p_musig, *p_Fx, *p_Fy, *p_gamma, *p_wr;
    cudaGetSymbolAddress((void**)&p_henc,  g_henc);
    cudaGetSymbolAddress((void**)&p_senc,  g_senc);
    cudaGetSymbolAddress((void**)&p_hdec,  g_hdec);
    cudaGetSymbolAddress((void**)&p_sdec,  g_sdec);
    cudaGetSymbolAddress((void**)&p_encin, g_encin);
    cudaGetSymbolAddress((void**)&p_decin, g_decin);
    cudaGetSymbolAddress((void**)&p_gates, g_gates);
    cudaGetSymbolAddress((void**)&p_musig, g_musig);
    cudaGetSymbolAddress((void**)&p_Fx,    g_Fx);
    cudaGetSymbolAddress((void**)&p_Fy,    g_Fy);
    cudaGetSymbolAddress((void**)&p_gamma, g_gamma);
    cudaGetSymbolAddress((void**)&p_wr,    g_wr);

    cudaFuncSetAttribute(gemm_mma, cudaFuncAttributeMaxDynamicSharedMemorySize,
                         GEMM_SMEM_BYTES);

    // init: zero canvas + states
    zero_kernel<<<4096, 256>>>(c, BATCH * AA * BB);
    zero_kernel<<<1024, 256>>>(p_henc, BATCH * ENC);
    zero_kernel<<<1024, 256>>>(p_senc, BATCH * ENC);
    zero_kernel<<<1024, 256>>>(p_hdec, BATCH * DEC);
    zero_kernel<<<1024, 256>>>(p_sdec, BATCH * DEC);

    dim3 grid_gate(25, 32);  // Nout=1600, M=4096
    dim3 grid_ms(2, 32);     // Nout=100
    dim3 grid_wr(3, 32);     // Nout=144

    for (int t = 0; t < T_STEPS; t++) {
        attn_kernel<<<BATCH, 128>>>(p_hdec, w_attn, b_attn, p_Fx, p_Fy, p_gamma,
                                    p_henc, p_encin, 1);
        glimpse_kernel<<<BATCH, 256>>>(x, c, p_Fx, p_Fy, p_gamma, p_encin);
        // encoder gates (3xTF32 mma.sync)
        gemm_mma<<<grid_gate, 256, GEMM_SMEM_BYTES>>>(
            p_encin, 1088, 1088, w_enc_ih, 688, w_enc_hh, 400,
            b_enc_ih, b_enc_hh, p_gates, 1600, 1600);
        lstm_pw<<<(BATCH * 400 + 255) / 256, 256>>>(p_gates, p_henc, p_senc);
        gemm_mma<<<grid_ms, 256, GEMM_SMEM_BYTES>>>(
            p_henc, 400, 400, w_mu, 400, (const float*)nullptr, 0,
            b_mu, (const float*)nullptr, p_musig, 200, 100);
        gemm_mma<<<grid_ms, 256, GEMM_SMEM_BYTES>>>(
            p_henc, 400, 400, w_sig, 400, (const float*)nullptr, 0,
            b_sig, (const float*)nullptr, p_musig + 100, 200, 100);
        z_kernel<<<(BATCH * 512 + 255) / 256, 256>>>(
            p_musig, eps + (size_t)t * BATCH * ZS, p_hdec, p_decin);
        // decoder gates (K padded 500->512 with zeros in decin)
        gemm_mma<<<grid_gate, 256, GEMM_SMEM_BYTES>>>(
            p_decin, 512, 512, w_dec_ih, 100, w_dec_hh, 400,
            b_dec_ih, b_dec_hh, p_gates, 1600, 1600);
        lstm_pw<<<(BATCH * 400 + 255) / 256, 256>>>(p_gates, p_hdec, p_sdec);
        attn_kernel<<<BATCH, 128>>>(p_hdec, w_attn, b_attn, p_Fx, p_Fy, p_gamma,
                                    p_henc, p_encin, 0);
        gemm_mma<<<grid_wr, 256, GEMM_SMEM_BYTES>>>(
            p_hdec, 400, 400, w_write, 400, (const float*)nullptr, 0,
            b_write, (const float*)nullptr, p_wr, 144, 144);
        write_kernel<<<BATCH, 256>>>(p_wr, p_Fx, p_Fy, p_gamma, c);
    }
}

// round 6
// speedup vs baseline: 1.6663x; 1.6663x over previous
#include <cuda_runtime.h>
#include <cstdint>

#define T_STEPS 16
#define NN 12
#define BATCH 4096
#define ZS 100
#define ENC 400
#define DEC 400

__device__ float g_henc[BATCH * ENC];
__device__ float g_senc[BATCH * ENC];
__device__ float g_hdec[BATCH * DEC];
__device__ float g_sdec[BATCH * DEC];
__device__ float g_encin[BATCH * 1088];
__device__ float g_decin[BATCH * 512];
__device__ float g_gates[BATCH * 1600];
__device__ float g_musig[BATCH * 200];
__device__ float g_wr[BATCH * NN * NN];

__device__ __forceinline__ float fsigm(float x) {
    return __fdividef(1.0f, 1.0f + __expf(-x));
}
__device__ __forceinline__ float ftanh(float x) {
    float t = __expf(-2.0f * x);
    return (1.0f - t) * __fdividef(1.0f, 1.0f + t);
}

__device__ __forceinline__ void split2(float v0, float v1, uint32_t& hw, uint32_t& lw) {
    asm("cvt.rn.bf16x2.f32 %0, %1, %2;" : "=r"(hw) : "f"(v1), "f"(v0));
    float h0 = __uint_as_float(hw << 16);
    float h1 = __uint_as_float(hw & 0xffff0000u);
    asm("cvt.rn.bf16x2.f32 %0, %1, %2;" : "=r"(lw) : "f"(v1 - h1), "f"(v0 - h0));
}

__device__ __forceinline__ void mma_bf16(float* d, const uint32_t* a, const uint32_t* b) {
    asm volatile(
        "mma.sync.aligned.m16n8k16.row.col.f32.bf16.bf16.f32 "
        "{%0,%1,%2,%3}, {%4,%5,%6,%7}, {%8,%9}, {%0,%1,%2,%3};\n"
        : "+f"(d[0]), "+f"(d[1]), "+f"(d[2]), "+f"(d[3])
        : "r"(a[0]), "r"(a[1]), "r"(a[2]), "r"(a[3]), "r"(b[0]), "r"(b[1]));
}

// ============ bf16x3 tensor GEMM: C = A @ Wrows^T + bias ============
// Rows of W from [W1|W2] (K-concat), or Wn2 for n>=Nsplit (N-concat, K2=0).
// Tile 128x64x32, 256 thr (8 warps 4Mx2N). uint2{hi,lo} per (kw,m).
#define APW 2176   // 16*136 uint2
#define BPW 1152   // 16*72 uint2
#define GEMM_SMEM ((2 * APW + 2 * BPW) * 8 + 256)

__global__ __launch_bounds__(256) void gemm_bf16(
    const float* __restrict__ A, int lda, int Ktot,
    const float* __restrict__ W1, int K1,
    const float* __restrict__ W2, int K2,
    const float* __restrict__ b1, const float* __restrict__ b2,
    const float* __restrict__ Wn2, const float* __restrict__ bn2, int Nsplit,
    float* __restrict__ C, int ldc, int Nout)
{
    extern __shared__ uint2 smp[];
    uint2* Ap = smp;
    uint2* Bp = smp + 2 * APW;
    float* sbias = (float*)(smp + 2 * APW + 2 * BPW);

    const int tid = threadIdx.x, lane = tid & 31, w = tid >> 5;
    const int r = lane >> 2, j = lane & 3;
    const int wm = (w >> 1) * 32, wn = (w & 1) * 32;
    const int m0 = blockIdx.y * 128, n0 = blockIdx.x * 64;
    const int K12 = K1 + K2;
    const int S = (Ktot + 31) >> 5;

    if (tid < 64) {
        int n = n0 + tid;
        float bv = 0.f;
        if (n < Nout) {
            if (Wn2 && n >= Nsplit) bv = bn2[n - Nsplit];
            else { bv = b1[n]; if (b2) bv += b2[n]; }
        }
        sbias[tid] = bv;
    }

    float d[2][4][4];
#pragma unroll
    for (int mi = 0; mi < 2; mi++)
#pragma unroll
        for (int ni = 0; ni < 4; ni++)
#pragma unroll
            for (int q = 0; q < 4; q++) d[mi][ni][q] = 0.f;

    float4 pa[4], pb[2];
    const float4 f4z = make_float4(0.f, 0.f, 0.f, 0.f);

#define LOAD_G(s) {                                                            \
    int k0g = (s) << 5;                                                        \
    _Pragma("unroll")                                                          \
    for (int cI = 0; cI < 4; cI++) {                                           \
        int fidx = tid + (cI << 8);                                            \
        int m = fidx >> 3;                                                     \
        int kg = k0g + ((fidx & 7) << 2);                                      \
        pa[cI] = (kg < Ktot)                                                   \
            ? *(const float4*)(A + (size_t)(m0 + m) * lda + kg) : f4z;         \
    }                                                                          \
    _Pragma("unroll")                                                          \
    for (int cI = 0; cI < 2; cI++) {                                           \
        int fidx = tid + (cI << 8);                                            \
        int n = fidx >> 3;                                                     \
        int kg = k0g + ((fidx & 7) << 2);                                      \
        float4 v = f4z;                                                        \
        int ng = n0 + n;                                                       \
        if (ng < Nout) {                                                       \
            const float* Wb = W1; int nr = ng;                                 \
            if (Wn2 && ng >= Nsplit) { Wb = Wn2; nr = ng - Nsplit; }           \
            if (kg < K1) v = *(const float4*)(Wb + (size_t)nr * K1 + kg);      \
            else if (W2 && kg < K12)                                           \
                v = *(const float4*)(W2 + (size_t)nr * K2 + (kg - K1));        \
        }                                                                      \
        pb[cI] = v;                                                            \
    } }

#define STORE_S(buf) {                                                         \
    uint2* ab = Ap + (buf) * APW;                                              \
    uint2* bb = Bp + (buf) * BPW;                                              \
    _Pragma("unroll")                                                          \
    for (int cI = 0; cI < 4; cI++) {                                           \
        int fidx = tid + (cI << 8);                                            \
        int m = fidx >> 3;                                                     \
        int kw0 = (fidx & 7) << 1, kw1 = kw0 + 1;                              \
        uint32_t h0, l0, h1, l1;                                               \
        split2(pa[cI].x, pa[cI].y, h0, l0);                                    \
        split2(pa[cI].z, pa[cI].w, h1, l1);                                    \
        ab[kw0 * 136 + (m ^ ((kw0 >> 2) << 2))] = make_uint2(h0, l0);          \
        ab[kw1 * 136 + (m ^ ((kw1 >> 2) << 2))] = make_uint2(h1, l1);          \
    }                                                                          \
    _Pragma("unroll")                                                          \
    for (int cI = 0; cI < 2; cI++) {                                           \
        int fidx = tid + (cI << 8);                                            \
        int n = fidx >> 3;                                                     \
        int kw0 = (fidx & 7) << 1, kw1 = kw0 + 1;                              \
        uint32_t h0, l0, h1, l1;                                               \
        split2(pb[cI].x, pb[cI].y, h0, l0);                                    \
        split2(pb[cI].z, pb[cI].w, h1, l1);                                    \
        bb[kw0 * 72 + (n ^ ((kw0 >> 2) << 2))] = make_uint2(h0, l0);           \
        bb[kw1 * 72 + (n ^ ((kw1 >> 2) << 2))] = make_uint2(h1, l1);           \
    } }

#define COMPUTE(buf) {                                                         \
    const uint2* ab = Ap + (buf) * APW;                                        \
    const uint2* bb = Bp + (buf) * BPW;                                        \
    _Pragma("unroll")                                                          \
    for (int kk = 0; kk < 2; kk++) {                                           \
        int kwa = kk * 8 + j, kwb = kwa + 4;                                   \
        int ga = (kwa >> 2) << 2, gb = (kwb >> 2) << 2;                        \
        uint32_t ah[2][4], al[2][4], bh[4][2], bl[4][2];                       \
        _Pragma("unroll")                                                      \
        for (int mi = 0; mi < 2; mi++) {                                       \
            int mb = wm + mi * 16 + r;                                         \
            uint2 w0 = ab[kwa * 136 + (mb ^ ga)];                              \
            uint2 w1 = ab[kwa * 136 + ((mb + 8) ^ ga)];                        \
            uint2 w2 = ab[kwb * 136 + (mb ^ gb)];                              \
            uint2 w3 = ab[kwb * 136 + ((mb + 8) ^ gb)];                        \
            ah[mi][0] = w0.x; ah[mi][1] = w1.x; ah[mi][2] = w2.x; ah[mi][3] = w3.x; \
            al[mi][0] = w0.y; al[mi][1] = w1.y; al[mi][2] = w2.y; al[mi][3] = w3.y; \
        }                                                                      \
        _Pragma("unroll")                                                      \
        for (int ni = 0; ni < 4; ni++) {                                       \
            int nb = wn + ni * 8 + r;                                          \
            uint2 u0 = bb[kwa * 72 + (nb ^ ga)];                               \
            uint2 u1 = bb[kwb * 72 + (nb ^ gb)];                               \
            bh[ni][0] = u0.x; bh[ni][1] = u1.x;                                \
            bl[ni][0] = u0.y; bl[ni][1] = u1.y;                                \
        }                                                                      \
        _Pragma("unroll")                                                      \
        for (int mi = 0; mi < 2; mi++)                                         \
            _Pragma("unroll")                                                  \
            for (int ni = 0; ni < 4; ni++) {                                   \
                mma_bf16(d[mi][ni], ah[mi], bl[ni]);                           \
                mma_bf16(d[mi][ni], al[mi], bh[ni]);                           \
                mma_bf16(d[mi][ni], ah[mi], bh[ni]);                           \
            }                                                                  \
    } }

    LOAD_G(0);
    STORE_S(0);
    __syncthreads();
    for (int s = 1; s < S; s++) {
        LOAD_G(s);
        COMPUTE((s - 1) & 1);
        STORE_S(s & 1);
        __syncthreads();
    }
    COMPUTE((S - 1) & 1);

#pragma unroll
    for (int mi = 0; mi < 2; mi++) {
        int row = m0 + wm + mi * 16 + r;
#pragma unroll
        for (int ni = 0; ni < 4; ni++) {
            int col = wn + ni * 8 + 2 * j;
            int gcol = n0 + col;
            if (gcol < Nout) {
                float bx = sbias[col], by = sbias[col + 1];
                *(float2*)(C + (size_t)row * ldc + gcol) =
                    make_float2(d[mi][ni][0] + bx, d[mi][ni][1] + by);
                *(float2*)(C + (size_t)(row + 8) * ldc + gcol) =
                    make_float2(d[mi][ni][2] + bx, d[mi][ni][3] + by);
            }
        }
    }
#undef LOAD_G
#undef STORE_S
#undef COMPUTE
}

__global__ void zero_kernel(float* p, int n) {
    int i = blockIdx.x * blockDim.x + threadIdx.x;
    int stride = gridDim.x * blockDim.x;
    for (; i < n; i += stride) p[i] = 0.0f;
}

// ============ fused attention + glimpse ============
__global__ __launch_bounds__(256) void glimpse_fused(
    const float* __restrict__ x, const float* __restrict__ c,
    const float* __restrict__ hdec, const float* __restrict__ henc,
    const float* __restrict__ w_attn, const float* __restrict__ b_attn,
    float* __restrict__ encin)
{
    int b = blockIdx.x;
    int tid = threadIdx.x;
    int lane = tid & 31, wid = tid >> 5;

    __shared__ float xs[4096], xh[4096];
    __shared__ float sFyT[64 * 16];       // [a][n]
    __shared__ float sFx[NN * 68];        // [n][a]
    __shared__ float tmp[2][NN * 64];
    __shared__ float red[5][8], pp[5], rsx[12], rsy[12];

    const float* xb = x + (size_t)b * 4096;
    const float* cb = c + (size_t)b * 4096;
    const float* h = hdec + (size_t)b * DEC;

    for (int i = tid; i < 1024; i += 256) {
        float4 xv = *(const float4*)(xb + i * 4);
        float4 cv = *(const float4*)(cb + i * 4);
        *(float4*)&xs[i * 4] = xv;
        float4 hx;
        hx.x = xv.x - fsigm(cv.x);
        hx.y = xv.y - fsigm(cv.y);
        hx.z = xv.z - fsigm(cv.z);
        hx.w = xv.w - fsigm(cv.w);
        *(float4*)&xh[i * 4] = hx;
    }

    float acc[5] = {0.f, 0.f, 0.f, 0.f, 0.f};
    for (int k = tid; k < DEC; k += 256) {
        float hv = h[k];
#pragma unroll
        for (int q = 0; q < 5; q++) acc[q] += hv * w_attn[q * DEC + k];
    }
#pragma unroll
    for (int q = 0; q < 5; q++)
#pragma unroll
        for (int off = 16; off > 0; off >>= 1)
            acc[q] += __shfl_xor_sync(0xffffffffu, acc[q], off);
    if (lane == 0)
#pragma unroll
        for (int q = 0; q < 5; q++) red[q][wid] = acc[q];
    __syncthreads();
    if (tid < 5) {
        float s = 0.f;
#pragma unroll
        for (int ww = 0; ww < 8; ww++) s += red[tid][ww];
        pp[tid] = s + b_attn[tid];
    }
    __syncthreads();

    float gx = 32.5f * (pp[0] + 1.0f);
    float gy = 32.5f * (pp[1] + 1.0f);
    float inv2s2 = __fdividef(1.0f, 2.0f * __expf(pp[2]));
    float delta = (63.0f / 11.0f) * __expf(pp[3]);
    float gamma = __expf(pp[4]);

    for (int e = tid; e < 768; e += 256) {
        int n = e >> 6, a = e & 63;
        float fa = (float)a;
        float base = ((float)n - 6.5f) * delta;
        float ty = (fa - (base + gy)) * inv2s2;
        sFyT[a * 16 + n] = __expf(-ty * ty);
        float tx = (fa - (base + gx)) * inv2s2;
        sFx[n * 68 + a] = __expf(-tx * tx);
    }
    __syncthreads();
    if (tid < 12) {
        float s = 0.f;
        for (int a = 0; a < 64; a++) s += sFx[tid * 68 + a];
        rsx[tid] = __fdividef(1.0f, s + 1e-9f);
    } else if (tid >= 16 && tid < 28) {
        int n = tid - 16;
        float s = 0.f;
        for (int a = 0; a < 64; a++) s += sFyT[a * 16 + n];
        rsy[n] = gamma * __fdividef(1.0f, s + 1e-9f);
    }
    __syncthreads();
    for (int e = tid; e < 768; e += 256) {
        int n = e >> 6, a = e & 63;
        sFx[n * 68 + a] *= rsx[n];
        sFyT[a * 16 + n] *= rsy[n];
    }
    __syncthreads();

    // phase 1: tmp[img][n][a] = sum_B Fy[n][B]*img[B][a]
    if (tid < 64) {
        int img = tid >> 5, half = (tid >> 4) & 1, aq = tid & 15;
        const float* src = img ? xh : xs;
        float a6[6][4];
#pragma unroll
        for (int nn = 0; nn < 6; nn++)
#pragma unroll
            for (int q = 0; q < 4; q++) a6[nn][q] = 0.f;
        for (int bi = 0; bi < 64; bi++) {
            float4 sv = *(const float4*)&src[bi * 64 + aq * 4];
            const float* fp = &sFyT[bi * 16 + half * 6];
#pragma unroll
            for (int nn = 0; nn < 6; nn++) {
                float f = fp[nn];
                a6[nn][0] += f * sv.x; a6[nn][1] += f * sv.y;
                a6[nn][2] += f * sv.z; a6[nn][3] += f * sv.w;
            }
        }
#pragma unroll
        for (int nn = 0; nn < 6; nn++)
            *(float4*)&tmp[img][(half * 6 + nn) * 64 + aq * 4] =
                make_float4(a6[nn][0], a6[nn][1], a6[nn][2], a6[nn][3]);
    }
    __syncthreads();

    // phase 2: r[img][n][m] = sum_a tmp[img][n][a]*Fx[m][a]
    float* ei = encin + (size_t)b * 1088;
    for (int o = tid; o < 288; o += 256) {
        int img = o >= 144;
        int rem = o - img * 144;
        int n = rem / 12, m = rem - n * 12;
        float s = 0.f;
#pragma unroll
        for (int aq = 0; aq < 16; aq++) {
            float4 t4 = *(const float4*)&tmp[img][n * 64 + aq * 4];
            float4 f4 = *(const float4*)&sFx[m * 68 + aq * 4];
            s += t4.x * f4.x + t4.y * f4.y + t4.z * f4.z + t4.w * f4.w;
        }
        ei[o] = s;
    }
    const float* he = henc + (size_t)b * ENC;
    for (int k = tid; k < 400; k += 256) {
        ei[288 + k] = h[k];
        ei[688 + k] = he[k];
    }
}

// ============ fused attention + canvas write ============
__global__ __launch_bounds__(256) void write_fused(
    const float* __restrict__ wrg, const float* __restrict__ hdec,
    const float* __restrict__ w_attn, const float* __restrict__ b_attn,
    float* __restrict__ c)
{
    int b = blockIdx.x;
    int tid = threadIdx.x;
    int lane = tid & 31, wid = tid >> 5;

    __shared__ float sFy[NN * 64], sFx[NN * 64];
    __shared__ float sw[NN * NN];
    __shared__ float tmpv[NN * 64];
    __shared__ float red[5][8], pp[5], rsx[12], rsy[12];

    const float* h = hdec + (size_t)b * DEC;

    float acc[5] = {0.f, 0.f, 0.f, 0.f, 0.f};
    for (int k = tid; k < DEC; k += 256) {
        float hv = h[k];
#pragma unroll
        for (int q = 0; q < 5; q++) acc[q] += hv * w_attn[q * DEC + k];
    }
#pragma unroll
    for (int q = 0; q < 5; q++)
#pragma unroll
        for (int off = 16; off > 0; off >>= 1)
            acc[q] += __shfl_xor_sync(0xffffffffu, acc[q], off);
    if (lane == 0)
#pragma unroll
        for (int q = 0; q < 5; q++) red[q][wid] = acc[q];
    if (tid < NN * NN) sw[tid] = wrg[(size_t)b * (NN * NN) + tid];
    __syncthreads();
    if (tid < 5) {
        float s = 0.f;
#pragma unroll
        for (int ww = 0; ww < 8; ww++) s += red[tid][ww];
        pp[tid] = s + b_attn[tid];
    }
    __syncthreads();

    float gx = 32.5f * (pp[0] + 1.0f);
    float gy = 32.5f * (pp[1] + 1.0f);
    float inv2s2 = __fdividef(1.0f, 2.0f * __expf(pp[2]));
    float delta = (63.0f / 11.0f) * __expf(pp[3]);
    float invgamma = __expf(-pp[4]);

    for (int e = tid; e < 768; e += 256) {
        int n = e >> 6, a = e & 63;
        float fa = (float)a;
        float base = ((float)n - 6.5f) * delta;
        float ty = (fa - (base + gy)) * inv2s2;
        sFy[n * 64 + a] = __expf(-ty * ty);
        float tx = (fa - (base + gx)) * inv2s2;
        sFx[n * 64 + a] = __expf(-tx * tx);
    }
    __syncthreads();
    if (tid < 12) {
        float s = 0.f;
        for (int a = 0; a < 64; a++) s += sFx[tid * 64 + a];
        rsx[tid] = __fdividef(1.0f, s + 1e-9f);
    } else if (tid >= 16 && tid < 28) {
        int n = tid - 16;
        float s = 0.f;
        for (int a = 0; a < 64; a++) s += sFy[n * 64 + a];
        rsy[n] = invgamma * __fdividef(1.0f, s + 1e-9f);
    }
    __syncthreads();
    for (int e = tid; e < 768; e += 256) {
        int n = e >> 6, a = e & 63;
        sFx[n * 64 + a] *= rsx[n];
        sFy[n * 64 + a] *= rsy[n];
    }
    __syncthreads();

    // tmp[m][Bi] = sum_n Fy[n][Bi] * w[n][m]
    for (int e = tid; e < NN * 64; e += 256) {
        int m = e >> 6, Bi = e & 63;
        float s = 0.f;
#pragma unroll
        for (int n = 0; n < NN; n++) s += sFy[n * 64 + Bi] * sw[n * NN + m];
        tmpv[e] = s;
    }
    __syncthreads();

    float* cb = c + (size_t)b * 4096;
    for (int p = tid; p < 1024; p += 256) {
        int Bi = p >> 4, aq = p & 15;
        float4 a4 = make_float4(0.f, 0.f, 0.f, 0.f);
#pragma unroll
        for (int m = 0; m < NN; m++) {
            float t = tmpv[m * 64 + Bi];
            float4 f4 = *(const float4*)&sFx[m * 64 + aq * 4];
            a4.x += t * f4.x; a4.y += t * f4.y;
            a4.z += t * f4.z; a4.w += t * f4.w;
        }
        float4 cv = *(float4*)&cb[Bi * 64 + aq * 4];
        cv.x += a4.x; cv.y += a4.y; cv.z += a4.z; cv.w += a4.w;
        *(float4*)&cb[Bi * 64 + aq * 4] = cv;
    }
}

// ============ LSTM pointwise ============
__global__ void lstm_pw(const float* __restrict__ gates,
                        float* __restrict__ h, float* __restrict__ s)
{
    int idx = blockIdx.x * blockDim.x + threadIdx.x;
    if (idx >= BATCH * 400) return;
    int b = idx / 400, u = idx - b * 400;
    const float* g = gates + (size_t)b * 1600;
    float gi = g[u], gf = g[400 + u], gg = g[800 + u], go = g[1200 + u];
    float c2 = fsigm(gf) * s[idx] + fsigm(gi) * ftanh(gg);
    s[idx] = c2;
    h[idx] = fsigm(go) * ftanh(c2);
}

// ============ z + decoder input (padded 512) ============
__global__ void z_kernel(const float* __restrict__ musig,
                         const float* __restrict__ eps_t,
                         const float* __restrict__ hdec,
                         float* __restrict__ decin)
{
    int idx = blockIdx.x * blockDim.x + threadIdx.x;
    if (idx >= BATCH * 512) return;
    int b = idx >> 9, j = idx & 511;
    float v;
    if (j < 100) {
        float mu = musig[(size_t)b * 200 + j];
        float ls = musig[(size_t)b * 200 + 100 + j];
        v = mu + __expf(ls) * eps_t[(size_t)b * 100 + j];
    } else if (j < 500) {
        v = hdec[(size_t)b * 400 + (j - 100)];
    } else v = 0.f;
    decin[idx] = v;
}

// ============ host ============
extern "C" void kernel_launch(void* const* d_in, const int* in_sizes, int n_in,
                              void* d_out, int out_size)
{
    const float* x        = (const float*)d_in[0];
    const float* eps      = (const float*)d_in[1];
    const float* w_enc_ih = (const float*)d_in[2];
    const float* w_enc_hh = (const float*)d_in[3];
    const float* b_enc_ih = (const float*)d_in[4];
    const float* b_enc_hh = (const float*)d_in[5];
    const float* w_dec_ih = (const float*)d_in[6];
    const float* w_dec_hh = (const float*)d_in[7];
    const float* b_dec_ih = (const float*)d_in[8];
    const float* b_dec_hh = (const float*)d_in[9];
    const float* w_mu     = (const float*)d_in[10];
    const float* b_mu     = (const float*)d_in[11];
    const float* w_sig    = (const float*)d_in[12];
    const float* b_sig    = (const float*)d_in[13];
    const float* w_attn   = (const float*)d_in[14];
    const float* b_attn   = (const float*)d_in[15];
    const float* w_write  = (const float*)d_in[16];
    const float* b_write  = (const float*)d_in[17];
    float* c = (float*)d_out;

    float *p_henc, *p_senc, *p_hdec, *p_sdec, *p_encin, *p_decin;
    float *p_gates, *p_musig, *p_wr;
    cudaGetSymbolAddress((void**)&p_henc,  g_henc);
    cudaGetSymbolAddress((void**)&p_senc,  g_senc);
    cudaGetSymbolAddress((void**)&p_hdec,  g_hdec);
    cudaGetSymbolAddress((void**)&p_sdec,  g_sdec);
    cudaGetSymbolAddress((void**)&p_encin, g_encin);
    cudaGetSymbolAddress((void**)&p_decin, g_decin);
    cudaGetSymbolAddress((void**)&p_gates, g_gates);
    cudaGetSymbolAddress((void**)&p_musig, g_musig);
    cudaGetSymbolAddress((void**)&p_wr,    g_wr);

    cudaFuncSetAttribute(gemm_bf16, cudaFuncAttributeMaxDynamicSharedMemorySize,
                         GEMM_SMEM);

    zero_kernel<<<4096, 256>>>(c, BATCH * 4096);
    zero_kernel<<<1024, 256>>>(p_henc, BATCH * ENC);
    zero_kernel<<<1024, 256>>>(p_senc, BATCH * ENC);
    zero_kernel<<<1024, 256>>>(p_hdec, BATCH * DEC);
    zero_kernel<<<1024, 256>>>(p_sdec, BATCH * DEC);

    dim3 grid_gate(25, 32);  // Nout=1600
    dim3 grid_ms(4, 32);     // Nout=200 (mu|sig merged)
    dim3 grid_wr(3, 32);     // Nout=144
    const float* nf = nullptr;

    for (int t = 0; t < T_STEPS; t++) {
        glimpse_fused<<<BATCH, 256>>>(x, c, p_hdec, p_henc, w_attn, b_attn,
                                      p_encin);
        gemm_bf16<<<grid_gate, 256, GEMM_SMEM>>>(
            p_encin, 1088, 1088, w_enc_ih, 688, w_enc_hh, 400,
            b_enc_ih, b_enc_hh, nf, nf, 0, p_gates, 1600, 1600);
        lstm_pw<<<6400, 256>>>(p_gates, p_henc, p_senc);
        gemm_bf16<<<grid_ms, 256, GEMM_SMEM>>>(
            p_henc, 400, 400, w_mu, 400, nf, 0,
            b_mu, nf, w_sig, b_sig, 100, p_musig, 200, 200);
        z_kernel<<<8192, 256>>>(p_musig, eps + (size_t)t * BATCH * ZS,
                                p_hdec, p_decin);
        gemm_bf16<<<grid_gate, 256, GEMM_SMEM>>>(
            p_decin, 512, 512, w_dec_ih, 100, w_dec_hh, 400,
            b_dec_ih, b_dec_hh, nf, nf, 0, p_gates, 1600, 1600);
        lstm_pw<<<6400, 256>>>(p_gates, p_hdec, p_sdec);
        gemm_bf16<<<grid_wr, 256, GEMM_SMEM>>>(
            p_hdec, 400, 400, w_write, 400, nf, 0,
            b_write, nf, nf, nf, 0, p_wr, 144, 144);
        write_fused<<<BATCH, 256>>>(p_wr, p_hdec, w_attn, b_attn, c);
    }
}

// round 7
// speedup vs baseline: 1.9452x; 1.1674x over previous
#include <cuda_runtime.h>
#include <cstdint>

#define T_STEPS 16
#define NN 12
#define BATCH 4096
#define ENC 400
#define DEC 400

// tile geometry: A stage = 16 kw x 136 = 2176 uint2; B stage = 16 x 72 = 1152
#define ATW 2176
#define BTW 1152
#define S_ENC 34
#define S_DEC 16
#define S_H 13

__device__ float g_henc[BATCH * ENC];
__device__ float g_senc[BATCH * ENC];
__device__ float g_hdec[BATCH * DEC];
__device__ float g_sdec[BATCH * DEC];
__device__ float g_gates[BATCH * 1600];
__device__ float g_musig[BATCH * 200];
__device__ float g_wrbuf[BATCH * 144];

__device__ uint2 g_encin_t[32 * S_ENC * ATW];
__device__ uint2 g_decin_t[32 * S_DEC * ATW];
__device__ uint2 g_henc_t[32 * S_H * ATW];
__device__ uint2 g_hdec_t[32 * S_H * ATW];

__device__ uint2 g_wenc_t[25 * S_ENC * BTW];
__device__ uint2 g_wdec_t[25 * S_DEC * BTW];
__device__ uint2 g_wms_t[4 * S_H * BTW];
__device__ uint2 g_wwr_t[3 * S_H * BTW];
__device__ float g_cb_enc[1600];
__device__ float g_cb_dec[1600];
__device__ float g_cb_ms[256];
__device__ float g_cb_wr[192];

__device__ __forceinline__ float fsigm(float x) {
    return __fdividef(1.0f, 1.0f + __expf(-x));
}
__device__ __forceinline__ float ftanh(float x) {
    float t = __expf(-2.0f * x);
    return (1.0f - t) * __fdividef(1.0f, 1.0f + t);
}

__device__ __forceinline__ void split2(float v0, float v1, uint32_t& hw, uint32_t& lw) {
    asm("cvt.rn.bf16x2.f32 %0, %1, %2;" : "=r"(hw) : "f"(v1), "f"(v0));
    float h0 = __uint_as_float(hw << 16);
    float h1 = __uint_as_float(hw & 0xffff0000u);
    asm("cvt.rn.bf16x2.f32 %0, %1, %2;" : "=r"(lw) : "f"(v1 - h1), "f"(v0 - h0));
}

__device__ __forceinline__ void mma_bf16(float* d, const uint32_t* a, const uint32_t* b) {
    asm volatile(
        "mma.sync.aligned.m16n8k16.row.col.f32.bf16.bf16.f32 "
        "{%0,%1,%2,%3}, {%4,%5,%6,%7}, {%8,%9}, {%0,%1,%2,%3};\n"
        : "+f"(d[0]), "+f"(d[1]), "+f"(d[2]), "+f"(d[3])
        : "r"(a[0]), "r"(a[1]), "r"(a[2]), "r"(a[3]), "r"(b[0]), "r"(b[1]));
}

// index of (batch row m, kw word) inside an A-tile array with S stages
__device__ __forceinline__ size_t a_idx(int S, int m, int kw) {
    return ((size_t)((m >> 7) * S + (kw >> 4))) * ATW +
           (kw & 15) * 136 + ((m & 127) ^ (((kw & 15) >> 2) << 2));
}

// ============ weight preconvert: split + pre-swizzled B tiles + bias ========
__global__ void prep_w(const float* __restrict__ W1, int K1,
                       const float* __restrict__ W2, int K2,
                       const float* __restrict__ b1, const float* __restrict__ b2,
                       const float* __restrict__ Wn2, const float* __restrict__ bn2,
                       int Nsplit, int Nout, int S,
                       uint2* __restrict__ Bt, float* __restrict__ cb)
{
    int nt = blockIdx.x, s = blockIdx.y;
    int K12 = K1 + K2;
    for (int e = threadIdx.x; e < 1024; e += blockDim.x) {
        int kwl = e >> 6, nl = e & 63;
        int n = nt * 64 + nl;
        const float* Wb = W1;
        int nr = n;
        if (Wn2 && n >= Nsplit) { Wb = Wn2; nr = n - Nsplit; }
        int k0 = (s * 16 + kwl) * 2;
        float f0 = 0.f, f1 = 0.f;
        if (n < Nout) {
            if (k0 < K1) f0 = Wb[(size_t)nr * K1 + k0];
            else if (k0 < K12) f0 = W2[(size_t)nr * K2 + (k0 - K1)];
            int k1 = k0 + 1;
            if (k1 < K1) f1 = Wb[(size_t)nr * K1 + k1];
            else if (k1 < K12) f1 = W2[(size_t)nr * K2 + (k1 - K1)];
        }
        uint32_t h, l;
        split2(f0, f1, h, l);
        Bt[((size_t)(nt * S + s)) * BTW + kwl * 72 + (nl ^ ((kwl >> 2) << 2))] =
            make_uint2(h, l);
        if (s == 0 && kwl == 0) {
            float bv = 0.f;
            if (n < Nout) {
                if (Wn2 && n >= Nsplit) bv = bn2[n - Nsplit];
                else { bv = b1[n]; if (b2) bv += b2[n]; }
            }
            cb[n] = bv;
        }
    }
}

// ============ tiled bf16x3 GEMM with cp.async pipeline ============
#define NSTG 3
#define STGW (ATW + BTW)
#define GEMM_SMEM (NSTG * STGW * 8 + 256)

#define CPA16(dst, src) \
    asm volatile("cp.async.cg.shared.global [%0], [%1], 16;" :: "r"(dst), "l"(src))

__global__ __launch_bounds__(256) void gemm_tiled(
    const uint2* __restrict__ At, const uint2* __restrict__ Bt,
    const float* __restrict__ cb, float* __restrict__ C,
    int ldc, int Nout, int S)
{
    extern __shared__ uint2 smp[];
    float* sbias = (float*)(smp + NSTG * STGW);
    const int tid = threadIdx.x, lane = tid & 31, w = tid >> 5;
    const int r = lane >> 2, j = lane & 3;
    const int wm = (w >> 1) * 32, wn = (w & 1) * 32;
    const int m0 = blockIdx.y * 128, n0 = blockIdx.x * 64;
    const uint2* Ag = At + (size_t)blockIdx.y * S * ATW;
    const uint2* Bg = Bt + (size_t)blockIdx.x * S * BTW;
    if (tid < 64) sbias[tid] = cb[n0 + tid];
    uint32_t smb = (uint32_t)__cvta_generic_to_shared(smp);

    float d[2][4][4];
#pragma unroll
    for (int mi = 0; mi < 2; mi++)
#pragma unroll
        for (int ni = 0; ni < 4; ni++)
#pragma unroll
            for (int q = 0; q < 4; q++) d[mi][ni][q] = 0.f;

#define ISSUE(s, buf) {                                                 \
    const char* ga = (const char*)(Ag + (size_t)(s) * ATW);             \
    const char* gb = (const char*)(Bg + (size_t)(s) * BTW);             \
    uint32_t da = smb + (buf) * (STGW * 8);                             \
    uint32_t db = da + ATW * 8;                                         \
    for (int i = tid; i < 1088; i += 256) CPA16(da + i * 16, ga + i * 16); \
    for (int i = tid; i < 576; i += 256)  CPA16(db + i * 16, gb + i * 16); \
    asm volatile("cp.async.commit_group;" ::: "memory"); }

#define COMPUTE(buf) {                                                  \
    const uint2* ab = smp + (buf) * STGW;                               \
    const uint2* bb = ab + ATW;                                         \
    _Pragma("unroll")                                                   \
    for (int kk = 0; kk < 2; kk++) {                                    \
        int kwa = kk * 8 + j, kwb = kwa + 4;                            \
        int ga2 = (kwa >> 2) << 2, gb2 = (kwb >> 2) << 2;               \
        uint32_t ah[2][4], al[2][4], bh[4][2], bl[4][2];                \
        _Pragma("unroll")                                               \
        for (int mi = 0; mi < 2; mi++) {                                \
            int mb = wm + mi * 16 + r;                                  \
            uint2 w0 = ab[kwa * 136 + (mb ^ ga2)];                      \
            uint2 w1 = ab[kwa * 136 + ((mb + 8) ^ ga2)];                \
            uint2 w2 = ab[kwb * 136 + (mb ^ gb2)];                      \
            uint2 w3 = ab[kwb * 136 + ((mb + 8) ^ gb2)];                \
            ah[mi][0] = w0.x; ah[mi][1] = w1.x; ah[mi][2] = w2.x; ah[mi][3] = w3.x; \
            al[mi][0] = w0.y; al[mi][1] = w1.y; al[mi][2] = w2.y; al[mi][3] = w3.y; \
        }                                                               \
        _Pragma("unroll")                                               \
        for (int ni = 0; ni < 4; ni++) {                                \
            int nb = wn + ni * 8 + r;                                   \
            uint2 u0 = bb[kwa * 72 + (nb ^ ga2)];                       \
            uint2 u1 = bb[kwb * 72 + (nb ^ gb2)];                       \
            bh[ni][0] = u0.x; bh[ni][1] = u1.x;                         \
            bl[ni][0] = u0.y; bl[ni][1] = u1.y;                         \
        }                                                               \
        _Pragma("unroll")                                               \
        for (int mi = 0; mi < 2; mi++)                                  \
            _Pragma("unroll")                                           \
            for (int ni = 0; ni < 4; ni++) {                            \
                mma_bf16(d[mi][ni], ah[mi], bl[ni]);                    \
                mma_bf16(d[mi][ni], al[mi], bh[ni]);                    \
                mma_bf16(d[mi][ni], ah[mi], bh[ni]);                    \
            }                                                           \
    } }

    ISSUE(0, 0);
    ISSUE(1, 1);
    for (int s = 0; s < S; s++) {
        if (s < S - 1) asm volatile("cp.async.wait_group 1;" ::: "memory");
        else           asm volatile("cp.async.wait_group 0;" ::: "memory");
        __syncthreads();
        if (s + 2 < S) ISSUE(s + 2, (s + 2) % 3);
        COMPUTE(s % 3);
    }

#pragma unroll
    for (int mi = 0; mi < 2; mi++) {
        int row = m0 + wm + mi * 16 + r;
#pragma unroll
        for (int ni = 0; ni < 4; ni++) {
            int col = wn + ni * 8 + 2 * j;
            int gcol = n0 + col;
            if (gcol < Nout) {
                float bx = sbias[col], by = sbias[col + 1];
                *(float2*)(C + (size_t)row * ldc + gcol) =
                    make_float2(d[mi][ni][0] + bx, d[mi][ni][1] + by);
                *(float2*)(C + (size_t)(row + 8) * ldc + gcol) =
                    make_float2(d[mi][ni][2] + bx, d[mi][ni][3] + by);
            }
        }
    }
#undef ISSUE
#undef COMPUTE
}

__global__ void zero_kernel(float* p, int n) {
    int i = blockIdx.x * blockDim.x + threadIdx.x;
    int stride = gridDim.x * blockDim.x;
    for (; i < n; i += stride) p[i] = 0.0f;
}

// ============ fused attention + glimpse -> encin tiles ============
__global__ __launch_bounds__(256) void glimpse_fused(
    const float* __restrict__ x, const float* __restrict__ c,
    const float* __restrict__ hdec, const float* __restrict__ henc,
    const float* __restrict__ w_attn, const float* __restrict__ b_attn,
    uint2* __restrict__ et)
{
    int b = blockIdx.x;
    int tid = threadIdx.x;
    int lane = tid & 31, wid = tid >> 5;

    __shared__ float xs[4096], xh[4096];
    __shared__ float sFyT[64 * 16];       // [a][n]
    __shared__ float sFx[NN * 68];        // [n][a]
    __shared__ float tmp[2][NN * 64];
    __shared__ float red[5][8], pp[5], rsx[12], rsy[12];

    const float* xb = x + (size_t)b * 4096;
    const float* cb = c + (size_t)b * 4096;
    const float* h = hdec + (size_t)b * DEC;

    for (int i = tid; i < 1024; i += 256) {
        float4 xv = *(const float4*)(xb + i * 4);
        float4 cv = *(const float4*)(cb + i * 4);
        *(float4*)&xs[i * 4] = xv;
        float4 hx;
        hx.x = xv.x - fsigm(cv.x);
        hx.y = xv.y - fsigm(cv.y);
        hx.z = xv.z - fsigm(cv.z);
        hx.w = xv.w - fsigm(cv.w);
        *(float4*)&xh[i * 4] = hx;
    }

    float acc[5] = {0.f, 0.f, 0.f, 0.f, 0.f};
    for (int k = tid; k < DEC; k += 256) {
        float hv = h[k];
#pragma unroll
        for (int q = 0; q < 5; q++) acc[q] += hv * w_attn[q * DEC + k];
    }
#pragma unroll
    for (int q = 0; q < 5; q++)
#pragma unroll
        for (int off = 16; off > 0; off >>= 1)
            acc[q] += __shfl_xor_sync(0xffffffffu, acc[q], off);
    if (lane == 0)
#pragma unroll
        for (int q = 0; q < 5; q++) red[q][wid] = acc[q];
    __syncthreads();
    if (tid < 5) {
        float s = 0.f;
#pragma unroll
        for (int ww = 0; ww < 8; ww++) s += red[tid][ww];
        pp[tid] = s + b_attn[tid];
    }
    __syncthreads();

    float gx = 32.5f * (pp[0] + 1.0f);
    float gy = 32.5f * (pp[1] + 1.0f);
    float inv2s2 = __fdividef(1.0f, 2.0f * __expf(pp[2]));
    float delta = (63.0f / 11.0f) * __expf(pp[3]);
    float gamma = __expf(pp[4]);

    for (int e = tid; e < 768; e += 256) {
        int n = e >> 6, a = e & 63;
        float fa = (float)a;
        float base = ((float)n - 6.5f) * delta;
        float ty = (fa - (base + gy)) * inv2s2;
        sFyT[a * 16 + n] = __expf(-ty * ty);
        float tx = (fa - (base + gx)) * inv2s2;
        sFx[n * 68 + a] = __expf(-tx * tx);
    }
    __syncthreads();
    if (tid < 12) {
        float s = 0.f;
        for (int a = 0; a < 64; a++) s += sFx[tid * 68 + a];
        rsx[tid] = __fdividef(1.0f, s + 1e-9f);
    } else if (tid >= 16 && tid < 28) {
        int n = tid - 16;
        float s = 0.f;
        for (int a = 0; a < 64; a++) s += sFyT[a * 16 + n];
        rsy[n] = gamma * __fdividef(1.0f, s + 1e-9f);
    }
    __syncthreads();
    for (int e = tid; e < 768; e += 256) {
        int n = e >> 6, a = e & 63;
        sFx[n * 68 + a] *= rsx[n];
        sFyT[a * 16 + n] *= rsy[n];
    }
    __syncthreads();

    // phase 1: tmp[img][n][a] = sum_B Fy[n][B]*img[B][a]
    if (tid < 64) {
        int img = tid >> 5, half = (tid >> 4) & 1, aq = tid & 15;
        const float* src = img ? xh : xs;
        float a6[6][4];
#pragma unroll
        for (int nn = 0; nn < 6; nn++)
#pragma unroll
            for (int q = 0; q < 4; q++) a6[nn][q] = 0.f;
        for (int bi = 0; bi < 64; bi++) {
            float4 sv = *(const float4*)&src[bi * 64 + aq * 4];
            const float* fp = &sFyT[bi * 16 + half * 6];
#pragma unroll
            for (int nn = 0; nn < 6; nn++) {
                float f = fp[nn];
                a6[nn][0] += f * sv.x; a6[nn][1] += f * sv.y;
                a6[nn][2] += f * sv.z; a6[nn][3] += f * sv.w;
            }
        }
#pragma unroll
        for (int nn = 0; nn < 6; nn++)
            *(float4*)&tmp[img][(half * 6 + nn) * 64 + aq * 4] =
                make_float4(a6[nn][0], a6[nn][1], a6[nn][2], a6[nn][3]);
    }
    __syncthreads();

    // phase 2: r pairs -> encin tiles kw 0..143
    for (int p = tid; p < 144; p += 256) {
        int img = p >= 72;
        int rem0 = 2 * p - img * 144;
        int n0q = rem0 / 12, m0q = rem0 - 12 * n0q;
        int n1q = n0q, m1q = m0q + 1;
        if (m1q == 12) { n1q++; m1q = 0; }
        float s0 = 0.f, s1 = 0.f;
#pragma unroll
        for (int aq = 0; aq < 16; aq++) {
            float4 t0 = *(const float4*)&tmp[img][n0q * 64 + aq * 4];
            float4 f0 = *(const float4*)&sFx[m0q * 68 + aq * 4];
            s0 += t0.x * f0.x + t0.y * f0.y + t0.z * f0.z + t0.w * f0.w;
            float4 t1 = *(const float4*)&tmp[img][n1q * 64 + aq * 4];
            float4 f1 = *(const float4*)&sFx[m1q * 68 + aq * 4];
            s1 += t1.x * f1.x + t1.y * f1.y + t1.z * f1.z + t1.w * f1.w;
        }
        uint32_t hh, ll;
        split2(s0, s1, hh, ll);
        et[a_idx(S_ENC, b, p)] = make_uint2(hh, ll);
    }
    // hdec segment kw 144..343, henc segment kw 344..543
    const float* he = henc + (size_t)b * ENC;
    for (int k2 = tid; k2 < 200; k2 += 256) {
        float2 hv = *(const float2*)(h + 2 * k2);
        uint32_t hh, ll;
        split2(hv.x, hv.y, hh, ll);
        et[a_idx(S_ENC, b, 144 + k2)] = make_uint2(hh, ll);
        float2 ev = *(const float2*)(he + 2 * k2);
        split2(ev.x, ev.y, hh, ll);
        et[a_idx(S_ENC, b, 344 + k2)] = make_uint2(hh, ll);
    }
}

// ============ fused attention + canvas write ============
__global__ __launch_bounds__(256) void write_fused(
    const float* __restrict__ wrg, const float* __restrict__ hdec,
    const float* __restrict__ w_attn, const float* __restrict__ b_attn,
    float* __restrict__ c)
{
    int b = blockIdx.x;
    int tid = threadIdx.x;
    int lane = tid & 31, wid = tid >> 5;

    __shared__ float sFy[NN * 64], sFx[NN * 64];
    __shared__ float sw[NN * NN];
    __shared__ float tmpv[NN * 64];
    __shared__ float red[5][8], pp[5], rsx[12], rsy[12];

    const float* h = hdec + (size_t)b * DEC;

    float acc[5] = {0.f, 0.f, 0.f, 0.f, 0.f};
    for (int k = tid; k < DEC; k += 256) {
        float hv = h[k];
#pragma unroll
        for (int q = 0; q < 5; q++) acc[q] += hv * w_attn[q * DEC + k];
    }
#pragma unroll
    for (int q = 0; q < 5; q++)
#pragma unroll
        for (int off = 16; off > 0; off >>= 1)
            acc[q] += __shfl_xor_sync(0xffffffffu, acc[q], off);
    if (lane == 0)
#pragma unroll
        for (int q = 0; q < 5; q++) red[q][wid] = acc[q];
    if (tid < NN * NN) sw[tid] = wrg[(size_t)b * (NN * NN) + tid];
    __syncthreads();
    if (tid < 5) {
        float s = 0.f;
#pragma unroll
        for (int ww = 0; ww < 8; ww++) s += red[tid][ww];
        pp[tid] = s + b_attn[tid];
    }
    __syncthreads();

    float gx = 32.5f * (pp[0] + 1.0f);
    float gy = 32.5f * (pp[1] + 1.0f);
    float inv2s2 = __fdividef(1.0f, 2.0f * __expf(pp[2]));
    float delta = (63.0f / 11.0f) * __expf(pp[3]);
    float invgamma = __expf(-pp[4]);

    for (int e = tid; e < 768; e += 256) {
        int n = e >> 6, a = e & 63;
        float fa = (float)a;
        float base = ((float)n - 6.5f) * delta;
        float ty = (fa - (base + gy)) * inv2s2;
        sFy[n * 64 + a] = __expf(-ty * ty);
        float tx = (fa - (base + gx)) * inv2s2;
        sFx[n * 64 + a] = __expf(-tx * tx);
    }
    __syncthreads();
    if (tid < 12) {
        float s = 0.f;
        for (int a = 0; a < 64; a++) s += sFx[tid * 64 + a];
        rsx[tid] = __fdividef(1.0f, s + 1e-9f);
    } else if (tid >= 16 && tid < 28) {
        int n = tid - 16;
        float s = 0.f;
        for (int a = 0; a < 64; a++) s += sFy[n * 64 + a];
        rsy[n] = invgamma * __fdividef(1.0f, s + 1e-9f);
    }
    __syncthreads();
    for (int e = tid; e < 768; e += 256) {
        int n = e >> 6, a = e & 63;
        sFx[n * 64 + a] *= rsx[n];
        sFy[n * 64 + a] *= rsy[n];
    }
    __syncthreads();

    for (int e = tid; e < NN * 64; e += 256) {
        int m = e >> 6, Bi = e & 63;
        float s = 0.f;
#pragma unroll
        for (int n = 0; n < NN; n++) s += sFy[n * 64 + Bi] * sw[n * NN + m];
        tmpv[e] = s;
    }
    __syncthreads();

    float* cbp = c + (size_t)b * 4096;
    for (int p = tid; p < 1024; p += 256) {
        int Bi = p >> 4, aq = p & 15;
        float4 a4 = make_float4(0.f, 0.f, 0.f, 0.f);
#pragma unroll
        for (int m = 0; m < NN; m++) {
            float t = tmpv[m * 64 + Bi];
            float4 f4 = *(const float4*)&sFx[m * 64 + aq * 4];
            a4.x += t * f4.x; a4.y += t * f4.y;
            a4.z += t * f4.z; a4.w += t * f4.w;
        }
        float4 cv = *(float4*)&cbp[Bi * 64 + aq * 4];
        cv.x += a4.x; cv.y += a4.y; cv.z += a4.z; cv.w += a4.w;
        *(float4*)&cbp[Bi * 64 + aq * 4] = cv;
    }
}

// ============ LSTM pointwise (pairs) + split-tile output ============
__global__ void lstm_pair(const float* __restrict__ gates,
                          float* __restrict__ h, float* __restrict__ s,
                          uint2* __restrict__ ht)
{
    int b = blockIdx.x;
    int kw = threadIdx.x;                  // 0..207
    if (kw < 200) {
        int u = kw * 2;
        const float* g = gates + (size_t)b * 1600;
        float2 gi = *(const float2*)(g + u);
        float2 gf = *(const float2*)(g + 400 + u);
        float2 gg = *(const float2*)(g + 800 + u);
        float2 go = *(const float2*)(g + 1200 + u);
        float2 sv = *(float2*)(s + (size_t)b * 400 + u);
        float c0 = fsigm(gf.x) * sv.x + fsigm(gi.x) * ftanh(gg.x);
        float c1 = fsigm(gf.y) * sv.y + fsigm(gi.y) * ftanh(gg.y);
        float h0 = fsigm(go.x) * ftanh(c0);
        float h1 = fsigm(go.y) * ftanh(c1);
        *(float2*)(s + (size_t)b * 400 + u) = make_float2(c0, c1);
        *(float2*)(h + (size_t)b * 400 + u) = make_float2(h0, h1);
        uint32_t hh, ll;
        split2(h0, h1, hh, ll);
        ht[a_idx(S_H, b, kw)] = make_uint2(hh, ll);
    } else {
        ht[a_idx(S_H, b, kw)] = make_uint2(0u, 0u);
    }
}

// ============ z + decoder-input tiles ============
__global__ void z_pair(const float* __restrict__ musig,
                       const float* __restrict__ eps_t,
                       const float* __restrict__ hdec,
                       uint2* __restrict__ dt)
{
    int idx = blockIdx.x * blockDim.x + threadIdx.x;
    if (idx >= BATCH * 256) return;
    int b = idx >> 8, kw = idx & 255;
    float v0 = 0.f, v1 = 0.f;
    if (kw < 50) {
        int u = kw * 2;
        const float* ms = musig + (size_t)b * 200;
        const float* ep = eps_t + (size_t)b * 100;
        v0 = ms[u] + __expf(ms[100 + u]) * ep[u];
        v1 = ms[u + 1] + __expf(ms[101 + u]) * ep[u + 1];
    } else if (kw < 250) {
        int u = kw * 2 - 100;
        float2 hv = *(const float2*)(hdec + (size_t)b * 400 + u);
        v0 = hv.x; v1 = hv.y;
    }
    uint32_t hh, ll;
    split2(v0, v1, hh, ll);
    dt[a_idx(S_DEC, b, kw)] = make_uint2(hh, ll);
}

// ============ host ============
extern "C" void kernel_launch(void* const* d_in, const int* in_sizes, int n_in,
                              void* d_out, int out_size)
{
    const float* x        = (const float*)d_in[0];
    const float* eps      = (const float*)d_in[1];
    const float* w_enc_ih = (const float*)d_in[2];
    const float* w_enc_hh = (const float*)d_in[3];
    const float* b_enc_ih = (const float*)d_in[4];
    const float* b_enc_hh = (const float*)d_in[5];
    const float* w_dec_ih = (const float*)d_in[6];
    const float* w_dec_hh = (const float*)d_in[7];
    const float* b_dec_ih = (const float*)d_in[8];
    const float* b_dec_hh = (const float*)d_in[9];
    const float* w_mu     = (const float*)d_in[10];
    const float* b_mu     = (const float*)d_in[11];
    const float* w_sig    = (const float*)d_in[12];
    const float* b_sig    = (const float*)d_in[13];
    const float* w_attn   = (const float*)d_in[14];
    const float* b_attn   = (const float*)d_in[15];
    const float* w_write  = (const float*)d_in[16];
    const float* b_write  = (const float*)d_in[17];
    float* c = (float*)d_out;

    float *p_henc, *p_senc, *p_hdec, *p_sdec, *p_gates, *p_musig, *p_wrbuf;
    uint2 *p_encin, *p_decin, *p_henct, *p_hdect;
    uint2 *p_wenc, *p_wdec, *p_wms, *p_wwr;
    float *p_cbenc, *p_cbdec, *p_cbms, *p_cbwr;
    cudaGetSymbolAddress((void**)&p_henc,  g_henc);
    cudaGetSymbolAddress((void**)&p_senc,  g_senc);
    cudaGetSymbolAddress((void**)&p_hdec,  g_hdec);
    cudaGetSymbolAddress((void**)&p_sdec,  g_sdec);
    cudaGetSymbolAddress((void**)&p_gates, g_gates);
    cudaGetSymbolAddress((void**)&p_musig, g_musig);
    cudaGetSymbolAddress((void**)&p_wrbuf, g_wrbuf);
    cudaGetSymbolAddress((void**)&p_encin, g_encin_t);
    cudaGetSymbolAddress((void**)&p_decin, g_decin_t);
    cudaGetSymbolAddress((void**)&p_henct, g_henc_t);
    cudaGetSymbolAddress((void**)&p_hdect, g_hdec_t);
    cudaGetSymbolAddress((void**)&p_wenc,  g_wenc_t);
    cudaGetSymbolAddress((void**)&p_wdec,  g_wdec_t);
    cudaGetSymbolAddress((void**)&p_wms,   g_wms_t);
    cudaGetSymbolAddress((void**)&p_wwr,   g_wwr_t);
    cudaGetSymbolAddress((void**)&p_cbenc, g_cb_enc);
    cudaGetSymbolAddress((void**)&p_cbdec, g_cb_dec);
    cudaGetSymbolAddress((void**)&p_cbms,  g_cb_ms);
    cudaGetSymbolAddress((void**)&p_cbwr,  g_cb_wr);

    cudaFuncSetAttribute(gemm_tiled, cudaFuncAttributeMaxDynamicSharedMemorySize,
                         GEMM_SMEM);

    const float* nf = nullptr;

    zero_kernel<<<4096, 256>>>(c, BATCH * 4096);
    zero_kernel<<<1024, 256>>>(p_senc, BATCH * ENC);
    zero_kernel<<<1024, 256>>>(p_sdec, BATCH * DEC);
    zero_kernel<<<1024, 256>>>(p_hdec, BATCH * DEC);
    zero_kernel<<<1024, 256>>>(p_henc, BATCH * ENC);

    prep_w<<<dim3(25, S_ENC), 256>>>(w_enc_ih, 688, w_enc_hh, 400,
                                     b_enc_ih, b_enc_hh, nf, nf, 0,
                                     1600, S_ENC, p_wenc, p_cbenc);
    prep_w<<<dim3(25, S_DEC), 256>>>(w_dec_ih, 100, w_dec_hh, 400,
                                     b_dec_ih, b_dec_hh, nf, nf, 0,
                                     1600, S_DEC, p_wdec, p_cbdec);
    prep_w<<<dim3(4, S_H), 256>>>(w_mu, 400, nf, 0,
                                  b_mu, nf, w_sig, b_sig, 100,
                                  200, S_H, p_wms, p_cbms);
    prep_w<<<dim3(3, S_H), 256>>>(w_write, 400, nf, 0,
                                  b_write, nf, nf, nf, 0,
                                  144, S_H, p_wwr, p_cbwr);

    dim3 grid_gate(25, 32), grid_ms(4, 32), grid_wr(3, 32);

    for (int t = 0; t < T_STEPS; t++) {
        glimpse_fused<<<BATCH, 256>>>(x, c, p_hdec, p_henc, w_attn, b_attn,
                                      p_encin);
        gemm_tiled<<<grid_gate, 256, GEMM_SMEM>>>(p_encin, p_wenc, p_cbenc,
                                                  p_gates, 1600, 1600, S_ENC);
        lstm_pair<<<BATCH, 208>>>(p_gates, p_henc, p_senc, p_henct);
        gemm_tiled<<<grid_ms, 256, GEMM_SMEM>>>(p_henct, p_wms, p_cbms,
                                                p_musig, 200, 200, S_H);
        z_pair<<<4096, 256>>>(p_musig, eps + (size_t)t * BATCH * 100,
                              p_hdec, p_decin);
        gemm_tiled<<<grid_gate, 256, GEMM_SMEM>>>(p_decin, p_wdec, p_cbdec,
                                                  p_gates, 1600, 1600, S_DEC);
        lstm_pair<<<BATCH, 208>>>(p_gates, p_hdec, p_sdec, p_hdect);
        gemm_tiled<<<grid_wr, 256, GEMM_SMEM>>>(p_hdect, p_wwr, p_cbwr,
                                                p_wrbuf, 144, 144, S_H);
        write_fused<<<BATCH, 256>>>(p_wrbuf, p_hdec, w_attn, b_attn, c);
    }
}